// round 6
// baseline (speedup 1.0000x reference)
#include <cuda_runtime.h>
#include <cuda_bf16.h>

// ZBL basis: per-edge screened Coulomb repulsion with polynomial cutoff,
// scatter-summed into receiver nodes.
//
// Inputs (metadata order):
//   d_in[0]: x               float32 [E, 1]   (E = 3,200,000)
//   d_in[1]: node_attrs      float32 [N, 10]  (N = 100,000)
//   d_in[2]: edge_index      int32   [2, E]
//   d_in[3]: atomic_numbers  int32   [10]
//   d_in[4]: covalent_radii  float32 [119]
// Output: V_ZBL float32 [N]
//
// Key points this revision:
//  - red.global.add.f32 asm has NO "memory" clobber: the RED result is never
//    read back, and the clobber was acting as a full compiler barrier 4x per
//    loop iteration, serializing the unrolled edges (killing MLP/ILP).
//  - Block-balanced contiguous chunking of the vec4 iteration space: every
//    block gets n4/grid (+/-1) iterations -> per-SM work is equal (the old
//    grid-stride split gave some SMs 3 iters/thread and others 2, a ~14% tax).
//  - uint4-vectorized Z-table smem copy (startup cost /4).

#define MAX_NODES 100352   // >= N, multiple of 16 for uint4 copies
#define N_ELEMS   10
#define NPAIR     (N_ELEMS * N_ELEMS)
#define EDGE_GRID 296      // 2 blocks/SM (smem-limited) x 148 SMs
#define NT        1024

__device__ unsigned char g_e[MAX_NODES];   // per-node element index 0..9

__device__ __forceinline__ float ex2f(float a) {
    float r; asm("ex2.approx.f32 %0, %1;" : "=f"(r) : "f"(a)); return r;
}
__device__ __forceinline__ float frcpf(float a) {
    float r; asm("rcp.approx.f32 %0, %1;" : "=f"(r) : "f"(a)); return r;
}

// Predicated no-return global float add. volatile (must not be deleted) but
// deliberately NO memory clobber: output buffer is write-only here, and a
// clobber would serialize the surrounding unrolled edges.
__device__ __forceinline__ void red_add_if(float* addr, float val, float rr) {
    asm volatile(
        "{\n\t"
        ".reg .pred p;\n\t"
        "setp.lt.f32 p, %1, 0f3F800000;\n\t"   // rr < 1.0f
        "@p red.global.add.f32 [%0], %2;\n\t"
        "}"
        :: "l"(addr), "f"(rr), "f"(val));
}

// ---------------------------------------------------------------------------
// Node prep: argmax over 10 attrs -> element index (u8); zero the output.
// ---------------------------------------------------------------------------
__global__ void node_prep_kernel(const float* __restrict__ attrs,
                                 float* __restrict__ out,
                                 int n_nodes, int out_n) {
    __shared__ float s[256 * N_ELEMS];
    int base = blockIdx.x * 256;
    int nloc = n_nodes - base;
    if (nloc > 256) nloc = 256;
    if (nloc > 0) {
        int total = nloc * N_ELEMS;                        // <= 2560 floats
        const float* src = attrs + (size_t)base * N_ELEMS; // 16B-aligned
        int nv4 = total >> 2;
        const float4* s4 = (const float4*)src;
        float4* d4 = (float4*)s;
        for (int k = threadIdx.x; k < nv4; k += 256) d4[k] = s4[k];
        for (int k = (nv4 << 2) + threadIdx.x; k < total; k += 256)
            s[k] = src[k];
    }
    __syncthreads();

    int i = base + threadIdx.x;
    if ((int)threadIdx.x < nloc) {
        const float* a = s + threadIdx.x * N_ELEMS;
        int best = 0;
        float bv = a[0];
#pragma unroll
        for (int j = 1; j < N_ELEMS; j++) {
            float v = a[j];
            if (v > bv) { bv = v; best = j; }
        }
        g_e[i] = (unsigned char)best;
    }
    if (i < out_n) out[i] = 0.0f;
}

// ---------------------------------------------------------------------------
// Edge kernel
// ---------------------------------------------------------------------------
__device__ __forceinline__ void process_edge(
    int s, int r, float xi,
    const unsigned char* __restrict__ s_e,
    const float* __restrict__ s_irm,
    const float* __restrict__ s_ia,
    const float* __restrict__ s_pf,
    float* __restrict__ out)
{
    int eu = s_e[s];
    int ev = s_e[r];
    int idx = eu * N_ELEMS + ev;
    float inv_rmax = s_irm[idx];
    float invA     = s_ia[idx];
    float pref     = s_pf[idx];

    float rr = xi * inv_rmax;
    float t  = xi * invA;

    // exp(-c*t) as ex2((-c*log2e)*t); constants folded at compile time
    const float K0 = -3.2f    * 1.44269504f;
    const float K1 = -0.9423f * 1.44269504f;
    const float K2 = -0.4028f * 1.44269504f;
    const float K3 = -0.2016f * 1.44269504f;
    float phi = 0.1818f  * ex2f(K0 * t)
              + 0.5099f  * ex2f(K1 * t)
              + 0.2802f  * ex2f(K2 * t)
              + 0.02817f * ex2f(K3 * t);

    // polynomial envelope, p=6: 1 - 28 r^6 + 48 r^7 - 21 r^8
    float r2 = rr * rr;
    float r3 = r2 * rr;
    float r6 = r3 * r3;
    float env = fmaf(-28.0f, r6, 1.0f);
    env = fmaf(48.0f, r6 * rr, env);
    env = fmaf(-21.0f, r6 * r2, env);

    float val = pref * phi * frcpf(xi) * env;
    red_add_if(out + r, val, rr);
}

__global__ void __launch_bounds__(NT, 1)
edge_kernel(const float* __restrict__ x,
            const int* __restrict__ ei,
            const int* __restrict__ atomic_numbers,
            const float* __restrict__ radii_g,
            float* __restrict__ out,
            int n_edges, int n_nodes) {
    extern __shared__ char smem[];
    float* s_irm = (float*)smem;           // NPAIR
    float* s_ia  = s_irm + NPAIR;          // NPAIR
    float* s_pf  = s_ia + NPAIR;           // NPAIR
    unsigned char* s_e = (unsigned char*)(s_pf + NPAIR);

    int tid = threadIdx.x;

    // Build SoA pair LUTs
    if (tid < NPAIR) {
        int i = tid / N_ELEMS, j = tid % N_ELEMS;
        int Zi = atomic_numbers[i], Zj = atomic_numbers[j];
        float Zif = (float)Zi, Zjf = (float)Zj;
        s_irm[tid] = 1.0f / (radii_g[Zi] + radii_g[Zj]);
        s_ia[tid]  = (powf(Zif, 0.3f) + powf(Zjf, 0.3f))
                     * (1.0f / (0.4543f * 0.529f));
        s_pf[tid]  = 0.5f * 14.3996f * Zif * Zjf;
    }
    // Copy element-index table into smem, 16B-wide (coalesced, L2-resident)
    {
        const uint4* ge = (const uint4*)g_e;
        uint4* se = (uint4*)s_e;
        int nvec = (n_nodes + 15) >> 4;
        for (int w = tid; w < nvec; w += NT) se[w] = ge[w];
    }
    __syncthreads();

    const int4*   si = (const int4*)ei;
    const int4*   ri = (const int4*)(ei + n_edges);
    const float4* x4 = (const float4*)x;
    int n4 = n_edges >> 2;

    // Block-balanced contiguous chunk: block b gets q (+1 if b < rem) vec4
    // iterations. Threads stride NT within the chunk (coalesced).
    int q   = n4 / gridDim.x;
    int rem = n4 - q * gridDim.x;
    int b   = blockIdx.x;
    int start = b * q + (b < rem ? b : rem);
    int end   = start + q + (b < rem ? 1 : 0);

    for (int g = start + tid; g < end; g += NT) {
        int4 ss = si[g];
        int4 rr = ri[g];
        float4 xx = x4[g];
        process_edge(ss.x, rr.x, xx.x, s_e, s_irm, s_ia, s_pf, out);
        process_edge(ss.y, rr.y, xx.y, s_e, s_irm, s_ia, s_pf, out);
        process_edge(ss.z, rr.z, xx.z, s_e, s_irm, s_ia, s_pf, out);
        process_edge(ss.w, rr.w, xx.w, s_e, s_irm, s_ia, s_pf, out);
    }
    // scalar tail (n_edges not divisible by 4)
    for (int i = (n4 << 2) + blockIdx.x * NT + tid; i < n_edges;
         i += gridDim.x * NT) {
        process_edge(ei[i], ei[n_edges + i], x[i], s_e, s_irm, s_ia, s_pf, out);
    }
}

extern "C" void kernel_launch(void* const* d_in, const int* in_sizes, int n_in,
                              void* d_out, int out_size) {
    const float* x              = (const float*)d_in[0];
    const float* node_attrs     = (const float*)d_in[1];
    const int*   edge_index     = (const int*)  d_in[2];
    const int*   atomic_numbers = (const int*)  d_in[3];
    const float* covalent_radii = (const float*)d_in[4];
    float* out = (float*)d_out;

    int n_edges = in_sizes[0];            // E
    int n_nodes = in_sizes[1] / N_ELEMS;  // N

    {
        int cover = n_nodes > out_size ? n_nodes : out_size;
        int blocks = (cover + 255) / 256;
        node_prep_kernel<<<blocks, 256>>>(node_attrs, out, n_nodes, out_size);
    }

    int smem_bytes = 3 * NPAIR * (int)sizeof(float) + MAX_NODES;
    cudaFuncSetAttribute(edge_kernel,
                         cudaFuncAttributeMaxDynamicSharedMemorySize,
                         smem_bytes);
    edge_kernel<<<EDGE_GRID, NT, smem_bytes>>>(x, edge_index, atomic_numbers,
                                               covalent_radii, out,
                                               n_edges, n_nodes);
}

// round 7
// speedup vs baseline: 1.0960x; 1.0960x over previous
#include <cuda_runtime.h>
#include <cuda_bf16.h>

// ZBL basis: per-edge screened Coulomb repulsion with polynomial cutoff,
// scatter-summed into receiver nodes.
//
// Inputs (metadata order):
//   d_in[0]: x               float32 [E, 1]   (E = 3,200,000)
//   d_in[1]: node_attrs      float32 [N, 10]  (N = 100,000)
//   d_in[2]: edge_index      int32   [2, E]
//   d_in[3]: atomic_numbers  int32   [10]
//   d_in[4]: covalent_radii  float32 [119]
// Output: V_ZBL float32 [N]
//
// HW model (validated R6): bound by L1TEX/LSU wavefront throughput, not
// issue/occupancy (halving occupancy changed nothing). Biggest reducible
// term: bank conflicts on the 3 scalar pair-LUT loads. Fix: replicate each
// 100-entry LUT 32x, one copy per smem bank (layout idx*32 + lane), so every
// lane hits its own bank -> conflict-free (5 cyc -> 1 cyc per load).
// Smem: 3*12.8KB replicated LUTs + 100KB u8 elem table = ~139KB, 1 block/SM.

#define MAX_NODES 100352   // >= N, multiple of 16 for uint4 copies
#define N_ELEMS   10
#define NPAIR     (N_ELEMS * N_ELEMS)
#define EDGE_GRID 148      // 1 block/SM (smem-limited), one exact wave
#define NT        1024

__device__ unsigned char g_e[MAX_NODES];   // per-node element index 0..9

__device__ __forceinline__ float ex2f(float a) {
    float r; asm("ex2.approx.f32 %0, %1;" : "=f"(r) : "f"(a)); return r;
}
__device__ __forceinline__ float frcpf(float a) {
    float r; asm("rcp.approx.f32 %0, %1;" : "=f"(r) : "f"(a)); return r;
}

// Predicated no-return global float add; no memory clobber (write-only out).
__device__ __forceinline__ void red_add_if(float* addr, float val, float rr) {
    asm volatile(
        "{\n\t"
        ".reg .pred p;\n\t"
        "setp.lt.f32 p, %1, 0f3F800000;\n\t"   // rr < 1.0f
        "@p red.global.add.f32 [%0], %2;\n\t"
        "}"
        :: "l"(addr), "f"(rr), "f"(val));
}

// ---------------------------------------------------------------------------
// Node prep: argmax over 10 attrs -> element index (u8); zero the output.
// ---------------------------------------------------------------------------
__global__ void node_prep_kernel(const float* __restrict__ attrs,
                                 float* __restrict__ out,
                                 int n_nodes, int out_n) {
    __shared__ float s[256 * N_ELEMS];
    int base = blockIdx.x * 256;
    int nloc = n_nodes - base;
    if (nloc > 256) nloc = 256;
    if (nloc > 0) {
        int total = nloc * N_ELEMS;                        // <= 2560 floats
        const float* src = attrs + (size_t)base * N_ELEMS; // 16B-aligned
        int nv4 = total >> 2;
        const float4* s4 = (const float4*)src;
        float4* d4 = (float4*)s;
        for (int k = threadIdx.x; k < nv4; k += 256) d4[k] = s4[k];
        for (int k = (nv4 << 2) + threadIdx.x; k < total; k += 256)
            s[k] = src[k];
    }
    __syncthreads();

    int i = base + threadIdx.x;
    if ((int)threadIdx.x < nloc) {
        const float* a = s + threadIdx.x * N_ELEMS;
        int best = 0;
        float bv = a[0];
#pragma unroll
        for (int j = 1; j < N_ELEMS; j++) {
            float v = a[j];
            if (v > bv) { bv = v; best = j; }
        }
        g_e[i] = (unsigned char)best;
    }
    if (i < out_n) out[i] = 0.0f;
}

// ---------------------------------------------------------------------------
// Edge kernel
// ---------------------------------------------------------------------------
__device__ __forceinline__ void process_edge(
    int s, int r, float xi, int lane,
    const unsigned char* __restrict__ s_e,
    const float* __restrict__ s_irm,   // replicated: [idx*32 + lane]
    const float* __restrict__ s_ia,
    const float* __restrict__ s_pf,
    float* __restrict__ out)
{
    int eu = s_e[s];
    int ev = s_e[r];
    int idx = ((eu * N_ELEMS + ev) << 5) + lane;   // bank == lane: conflict-free
    float inv_rmax = s_irm[idx];
    float invA     = s_ia[idx];
    float pref     = s_pf[idx];

    float rr = xi * inv_rmax;
    float t  = xi * invA;

    // exp(-c*t) as ex2((-c*log2e)*t); constants folded at compile time
    const float K0 = -3.2f    * 1.44269504f;
    const float K1 = -0.9423f * 1.44269504f;
    const float K2 = -0.4028f * 1.44269504f;
    const float K3 = -0.2016f * 1.44269504f;
    float phi = 0.1818f  * ex2f(K0 * t)
              + 0.5099f  * ex2f(K1 * t)
              + 0.2802f  * ex2f(K2 * t)
              + 0.02817f * ex2f(K3 * t);

    // polynomial envelope, p=6: 1 - 28 r^6 + 48 r^7 - 21 r^8
    float r2 = rr * rr;
    float r3 = r2 * rr;
    float r6 = r3 * r3;
    float env = fmaf(-28.0f, r6, 1.0f);
    env = fmaf(48.0f, r6 * rr, env);
    env = fmaf(-21.0f, r6 * r2, env);

    float val = pref * phi * frcpf(xi) * env;
    red_add_if(out + r, val, rr);
}

__global__ void __launch_bounds__(NT, 1)
edge_kernel(const float* __restrict__ x,
            const int* __restrict__ ei,
            const int* __restrict__ atomic_numbers,
            const float* __restrict__ radii_g,
            float* __restrict__ out,
            int n_edges, int n_nodes) {
    extern __shared__ char smem[];
    float* s_irm = (float*)smem;                 // NPAIR*32 (bank-replicated)
    float* s_ia  = s_irm + NPAIR * 32;           // NPAIR*32
    float* s_pf  = s_ia + NPAIR * 32;            // NPAIR*32
    unsigned char* s_e = (unsigned char*)(s_pf + NPAIR * 32);

    int tid = threadIdx.x;
    int lane = tid & 31;

    // Build bank-replicated SoA pair LUTs: entry idx lives at [idx*32 + c]
    // for every bank c (32 copies). Thread tid<NPAIR computes entry tid and
    // writes its 32 copies (stride-1 words: conflict-free).
    if (tid < NPAIR) {
        int i = tid / N_ELEMS, j = tid % N_ELEMS;
        int Zi = atomic_numbers[i], Zj = atomic_numbers[j];
        float Zif = (float)Zi, Zjf = (float)Zj;
        float irm = 1.0f / (radii_g[Zi] + radii_g[Zj]);
        float ia  = (powf(Zif, 0.3f) + powf(Zjf, 0.3f))
                    * (1.0f / (0.4543f * 0.529f));
        float pf  = 0.5f * 14.3996f * Zif * Zjf;
        int base = tid << 5;
#pragma unroll
        for (int c = 0; c < 32; c++) {
            s_irm[base + c] = irm;
            s_ia[base + c]  = ia;
            s_pf[base + c]  = pf;
        }
    }
    // Copy element-index table into smem, 16B-wide (coalesced, L2-resident)
    {
        const uint4* ge = (const uint4*)g_e;
        uint4* se = (uint4*)s_e;
        int nvec = (n_nodes + 15) >> 4;
        for (int w = tid; w < nvec; w += NT) se[w] = ge[w];
    }
    __syncthreads();

    const int4*   si = (const int4*)ei;
    const int4*   ri = (const int4*)(ei + n_edges);
    const float4* x4 = (const float4*)x;
    int n4 = n_edges >> 2;

    // Block-balanced contiguous chunk: block b gets q (+1 if b < rem) vec4
    // iterations. Threads stride NT within the chunk (coalesced).
    int q   = n4 / gridDim.x;
    int rem = n4 - q * gridDim.x;
    int b   = blockIdx.x;
    int start = b * q + (b < rem ? b : rem);
    int end   = start + q + (b < rem ? 1 : 0);

    for (int g = start + tid; g < end; g += NT) {
        int4 ss = si[g];
        int4 rr = ri[g];
        float4 xx = x4[g];
        process_edge(ss.x, rr.x, xx.x, lane, s_e, s_irm, s_ia, s_pf, out);
        process_edge(ss.y, rr.y, xx.y, lane, s_e, s_irm, s_ia, s_pf, out);
        process_edge(ss.z, rr.z, xx.z, lane, s_e, s_irm, s_ia, s_pf, out);
        process_edge(ss.w, rr.w, xx.w, lane, s_e, s_irm, s_ia, s_pf, out);
    }
    // scalar tail (n_edges not divisible by 4)
    for (int i = (n4 << 2) + blockIdx.x * NT + tid; i < n_edges;
         i += gridDim.x * NT) {
        process_edge(ei[i], ei[n_edges + i], x[i], lane,
                     s_e, s_irm, s_ia, s_pf, out);
    }
}

extern "C" void kernel_launch(void* const* d_in, const int* in_sizes, int n_in,
                              void* d_out, int out_size) {
    const float* x              = (const float*)d_in[0];
    const float* node_attrs     = (const float*)d_in[1];
    const int*   edge_index     = (const int*)  d_in[2];
    const int*   atomic_numbers = (const int*)  d_in[3];
    const float* covalent_radii = (const float*)d_in[4];
    float* out = (float*)d_out;

    int n_edges = in_sizes[0];            // E
    int n_nodes = in_sizes[1] / N_ELEMS;  // N

    {
        int cover = n_nodes > out_size ? n_nodes : out_size;
        int blocks = (cover + 255) / 256;
        node_prep_kernel<<<blocks, 256>>>(node_attrs, out, n_nodes, out_size);
    }

    int smem_bytes = 3 * NPAIR * 32 * (int)sizeof(float) + MAX_NODES;
    cudaFuncSetAttribute(edge_kernel,
                         cudaFuncAttributeMaxDynamicSharedMemorySize,
                         smem_bytes);
    edge_kernel<<<EDGE_GRID, NT, smem_bytes>>>(x, edge_index, atomic_numbers,
                                               covalent_radii, out,
                                               n_edges, n_nodes);
}